// round 9
// baseline (speedup 1.0000x reference)
#include <cuda_runtime.h>
#include <cstdint>

// TTStack: out[b, (a c d), (i j l)] = sum_{k1,k2} c0[idx,a,i,k1] * c1[idx,k1,c,j,k2] * c2[idx,k2,d,l]
// Shapes: c0 [1000,8,8,16], c1 [1000,16,8,8,16], c2 [1000,16,8,8], indices [512] int32
// Output: [512, 512, 512] fp32 (512 MB) — store-stream + fp32-FMA bound.

#define THREADS 512
#define C1_PAD 20   // pad k2 row 16 -> 20 floats: conflict-free LDS.128 across j

static constexpr int SM_C1 = 16 * 8 * 8 * C1_PAD;  // 20480 floats
static constexpr int SM_C2 = 16 * 8 * 8;           // 1024 floats
static constexpr int SM_C0 = 8 * 16;               // 128 floats (row a of c0)
static constexpr size_t SMEM_BYTES = (size_t)(SM_C1 + SM_C2 + SM_C0) * sizeof(float);

typedef unsigned long long ull;

// Packed f32x2 FMA (Blackwell sm_103a): two fp32 FMAs per instruction.
__device__ __forceinline__ ull ffma2(ull a, ull b, ull c) {
    ull d;
    asm("fma.rn.f32x2 %0, %1, %2, %3;" : "=l"(d) : "l"(a), "l"(b), "l"(c));
    return d;
}
__device__ __forceinline__ ull pack2(float x, float y) {
    ull r;
    asm("mov.b64 %0, {%1, %2};" : "=l"(r) : "f"(x), "f"(y));
    return r;
}
__device__ __forceinline__ float2 unpack2(ull v) {
    float2 r;
    asm("mov.b64 {%0, %1}, %2;" : "=f"(r.x), "=f"(r.y) : "l"(v));
    return r;
}

__global__ __launch_bounds__(THREADS, 2)
void tt_stack_kernel(const float* __restrict__ core0,
                     const float* __restrict__ core1,
                     const float* __restrict__ core2,
                     const int*   __restrict__ indices,
                     float*       __restrict__ out)
{
    extern __shared__ float smem[];
    float* sC1 = smem;                   // [k1][c][j][k2 padded to 20]
    float* sC2 = smem + SM_C1;           // [k2][d][l]
    float* sC0 = smem + SM_C1 + SM_C2;   // [i][k1]  (row a of c0)

    const int b   = blockIdx.y;
    const int a   = blockIdx.x;
    const int tid = threadIdx.x;
    const int idx = indices[b];

    // ---- stage cores into smem (float4, coalesced) ----
    {
        const float4* g1 = reinterpret_cast<const float4*>(core1 + (size_t)idx * 16384);
        float4* s1 = reinterpret_cast<float4*>(sC1);
        #pragma unroll
        for (int u = tid; u < 4096; u += THREADS) {
            int row = u >> 2;      // (k1*8+c)*8+j
            int q   = u & 3;       // which float4 within the 16-float k2 row
            s1[row * (C1_PAD / 4) + q] = g1[u];
        }
        if (tid < 256) {
            reinterpret_cast<float4*>(sC2)[tid] =
                reinterpret_cast<const float4*>(core2 + (size_t)idx * 1024)[tid];
        }
        if (tid < 32) {
            reinterpret_cast<float4*>(sC0)[tid] =
                reinterpret_cast<const float4*>(core0 + (size_t)idx * 1024 + a * 128)[tid];
        }
    }
    __syncthreads();

    const int c = tid >> 6;
    const int i = (tid >> 3) & 7;
    const int j = tid & 7;

    // ---- stage 1: t[k2] = sum_k1 c0[a,i,k1] * c1[k1,c,j,k2]  (f32x2 over k2 pairs) ----
    ull t2[8];
    #pragma unroll
    for (int q = 0; q < 8; q++) t2[q] = 0ull;   // (0.0f, 0.0f)

    const float* c0row = sC0 + i * 16;
    const int rowbase = (c * 8 + j) * C1_PAD;
    #pragma unroll
    for (int k1 = 0; k1 < 16; k1++) {
        float av = c0row[k1];
        ull avv = pack2(av, av);
        const ulonglong2* p =
            reinterpret_cast<const ulonglong2*>(sC1 + k1 * (64 * C1_PAD) + rowbase);
        #pragma unroll
        for (int q = 0; q < 4; q++) {
            ulonglong2 v = p[q];
            t2[2 * q]     = ffma2(avv, v.x, t2[2 * q]);
            t2[2 * q + 1] = ffma2(avv, v.y, t2[2 * q + 1]);
        }
    }

    // duplicate each t[k2] into both f32x2 lanes for stage 2
    ull tdup[16];
    #pragma unroll
    for (int q = 0; q < 8; q++) {
        float2 v = unpack2(t2[q]);
        tdup[2 * q]     = pack2(v.x, v.x);
        tdup[2 * q + 1] = pack2(v.y, v.y);
    }

    // ---- stage 2: out[d,l] = sum_k2 t[k2] * c2[k2,d,l]  (f32x2 over l pairs) ----
    // row = (a*8+c)*8+d, col = i*64 + j*8 + l
    float* ob = out + ((size_t)b * 512 + (size_t)((a * 8 + c) * 8)) * 512
                    + (size_t)(i * 64 + j * 8);

    #pragma unroll
    for (int d = 0; d < 8; d++) {
        ull acc0 = 0ull, acc1 = 0ull, acc2 = 0ull, acc3 = 0ull;
        const ulonglong2* q2 = reinterpret_cast<const ulonglong2*>(sC2 + d * 8);
        #pragma unroll
        for (int k2 = 0; k2 < 16; k2++) {
            // sC2 element (k2*8+d)*8 .. +7  -> ulonglong2 indices k2*16, k2*16+1 (rel. to d*2)
            ulonglong2 v0 = q2[k2 * 16];
            ulonglong2 v1 = q2[k2 * 16 + 1];
            ull tb = tdup[k2];
            acc0 = ffma2(tb, v0.x, acc0);
            acc1 = ffma2(tb, v0.y, acc1);
            acc2 = ffma2(tb, v1.x, acc2);
            acc3 = ffma2(tb, v1.y, acc3);
        }
        float2 f0 = unpack2(acc0), f1 = unpack2(acc1);
        float2 f2 = unpack2(acc2), f3 = unpack2(acc3);
        float* row = ob + (size_t)d * 512;
        reinterpret_cast<float4*>(row)[0] = make_float4(f0.x, f0.y, f1.x, f1.y);
        reinterpret_cast<float4*>(row)[1] = make_float4(f2.x, f2.y, f3.x, f3.y);
    }
}

extern "C" void kernel_launch(void* const* d_in, const int* in_sizes, int n_in,
                              void* d_out, int out_size)
{
    const float* core0   = (const float*)d_in[0];
    const float* core1   = (const float*)d_in[1];
    const float* core2   = (const float*)d_in[2];
    const int*   indices = (const int*)d_in[3];
    const int B = in_sizes[3];   // 512

    // Idempotent, not a stream op — safe under graph capture.
    cudaFuncSetAttribute(tt_stack_kernel,
                         cudaFuncAttributeMaxDynamicSharedMemorySize,
                         (int)SMEM_BYTES);

    dim3 grid(8, B, 1);          // (a, b)
    tt_stack_kernel<<<grid, THREADS, SMEM_BYTES>>>(core0, core1, core2, indices,
                                                   (float*)d_out);
}

// round 10
// speedup vs baseline: 1.0021x; 1.0021x over previous
#include <cuda_runtime.h>
#include <cstdint>

// TTStack: out[b, (a c d), (i j l)] = sum_{k1,k2} c0[idx,a,i,k1] * c1[idx,k1,c,j,k2] * c2[idx,k2,d,l]
// Shapes: c0 [1000,8,8,16], c1 [1000,16,8,8,16], c2 [1000,16,8,8], indices [512] int32
// Output: [512, 512, 512] fp32 (512 MB) — store-stream + fp32-FMA bound.

#define THREADS 512
#define C1_PAD 20   // pad k2 row 16 -> 20 floats: conflict-free LDS.128 across j

static constexpr int SM_C1 = 16 * 8 * 8 * C1_PAD;  // 20480 floats
static constexpr int SM_C2 = 16 * 8 * 8;           // 1024 floats
static constexpr int SM_C0 = 8 * 16;               // 128 floats (row a of c0)
static constexpr size_t SMEM_BYTES = (size_t)(SM_C1 + SM_C2 + SM_C0) * sizeof(float);

typedef unsigned long long ull;

// Packed f32x2 FMA (Blackwell sm_103a): two fp32 FMAs per instruction.
__device__ __forceinline__ ull ffma2(ull a, ull b, ull c) {
    ull d;
    asm("fma.rn.f32x2 %0, %1, %2, %3;" : "=l"(d) : "l"(a), "l"(b), "l"(c));
    return d;
}
__device__ __forceinline__ ull pack2(float x, float y) {
    ull r;
    asm("mov.b64 %0, {%1, %2};" : "=l"(r) : "f"(x), "f"(y));
    return r;
}
__device__ __forceinline__ float2 unpack2(ull v) {
    float2 r;
    asm("mov.b64 {%0, %1}, %2;" : "=f"(r.x), "=f"(r.y) : "l"(v));
    return r;
}

__global__ __launch_bounds__(THREADS, 2)
void tt_stack_kernel(const float* __restrict__ core0,
                     const float* __restrict__ core1,
                     const float* __restrict__ core2,
                     const int*   __restrict__ indices,
                     float*       __restrict__ out)
{
    extern __shared__ float smem[];
    float* sC1 = smem;                   // [k1][c][j][k2 padded to 20]
    float* sC2 = smem + SM_C1;           // [k2][d][l]
    float* sC0 = smem + SM_C1 + SM_C2;   // [i][k1]  (row a of c0)

    const int b   = blockIdx.y;
    const int a   = blockIdx.x;
    const int tid = threadIdx.x;
    const int idx = indices[b];

    // ---- stage cores into smem (float4, coalesced) ----
    {
        const float4* g1 = reinterpret_cast<const float4*>(core1 + (size_t)idx * 16384);
        float4* s1 = reinterpret_cast<float4*>(sC1);
        #pragma unroll
        for (int u = tid; u < 4096; u += THREADS) {
            int row = u >> 2;      // (k1*8+c)*8+j
            int q   = u & 3;       // which float4 within the 16-float k2 row
            s1[row * (C1_PAD / 4) + q] = g1[u];
        }
        if (tid < 256) {
            reinterpret_cast<float4*>(sC2)[tid] =
                reinterpret_cast<const float4*>(core2 + (size_t)idx * 1024)[tid];
        }
        if (tid < 32) {
            reinterpret_cast<float4*>(sC0)[tid] =
                reinterpret_cast<const float4*>(core0 + (size_t)idx * 1024 + a * 128)[tid];
        }
    }
    __syncthreads();

    const int c = tid >> 6;
    const int i = (tid >> 3) & 7;
    const int j = tid & 7;

    // ---- stage 1: t[k2] = sum_k1 c0[a,i,k1] * c1[k1,c,j,k2]  (f32x2 over k2 pairs) ----
    ull t2[8];
    #pragma unroll
    for (int q = 0; q < 8; q++) t2[q] = 0ull;   // (0.0f, 0.0f)

    const float* c0row = sC0 + i * 16;
    const int rowbase = (c * 8 + j) * C1_PAD;
    #pragma unroll
    for (int k1 = 0; k1 < 16; k1++) {
        float av = c0row[k1];
        ull avv = pack2(av, av);
        const ulonglong2* p =
            reinterpret_cast<const ulonglong2*>(sC1 + k1 * (64 * C1_PAD) + rowbase);
        #pragma unroll
        for (int q = 0; q < 4; q++) {
            ulonglong2 v = p[q];
            t2[2 * q]     = ffma2(avv, v.x, t2[2 * q]);
            t2[2 * q + 1] = ffma2(avv, v.y, t2[2 * q + 1]);
        }
    }

    // duplicate each t[k2] into both f32x2 lanes for stage 2
    ull tdup[16];
    #pragma unroll
    for (int q = 0; q < 8; q++) {
        float2 v = unpack2(t2[q]);
        tdup[2 * q]     = pack2(v.x, v.x);
        tdup[2 * q + 1] = pack2(v.y, v.y);
    }

    // ---- stage 2: out[d,l] = sum_k2 t[k2] * c2[k2,d,l]  (f32x2 over l pairs) ----
    // row = (a*8+c)*8+d, col = i*64 + j*8 + l
    float* ob = out + ((size_t)b * 512 + (size_t)((a * 8 + c) * 8)) * 512
                    + (size_t)(i * 64 + j * 8);

    #pragma unroll
    for (int d = 0; d < 8; d++) {
        ull acc0 = 0ull, acc1 = 0ull, acc2 = 0ull, acc3 = 0ull;
        const ulonglong2* q2 = reinterpret_cast<const ulonglong2*>(sC2 + d * 8);
        #pragma unroll
        for (int k2 = 0; k2 < 16; k2++) {
            // sC2 element (k2*8+d)*8 .. +7  -> ulonglong2 indices k2*16, k2*16+1 (rel. to d*2)
            ulonglong2 v0 = q2[k2 * 16];
            ulonglong2 v1 = q2[k2 * 16 + 1];
            ull tb = tdup[k2];
            acc0 = ffma2(tb, v0.x, acc0);
            acc1 = ffma2(tb, v0.y, acc1);
            acc2 = ffma2(tb, v1.x, acc2);
            acc3 = ffma2(tb, v1.y, acc3);
        }
        float2 f0 = unpack2(acc0), f1 = unpack2(acc1);
        float2 f2 = unpack2(acc2), f3 = unpack2(acc3);
        float* row = ob + (size_t)d * 512;
        reinterpret_cast<float4*>(row)[0] = make_float4(f0.x, f0.y, f1.x, f1.y);
        reinterpret_cast<float4*>(row)[1] = make_float4(f2.x, f2.y, f3.x, f3.y);
    }
}

extern "C" void kernel_launch(void* const* d_in, const int* in_sizes, int n_in,
                              void* d_out, int out_size)
{
    const float* core0   = (const float*)d_in[0];
    const float* core1   = (const float*)d_in[1];
    const float* core2   = (const float*)d_in[2];
    const int*   indices = (const int*)d_in[3];
    const int B = in_sizes[3];   // 512

    // Idempotent, not a stream op — safe under graph capture.
    cudaFuncSetAttribute(tt_stack_kernel,
                         cudaFuncAttributeMaxDynamicSharedMemorySize,
                         (int)SMEM_BYTES);

    dim3 grid(8, B, 1);          // (a, b)
    tt_stack_kernel<<<grid, THREADS, SMEM_BYTES>>>(core0, core1, core2, indices,
                                                   (float*)d_out);
}